// round 1
// baseline (speedup 1.0000x reference)
#include <cuda_runtime.h>

#define BB 64
#define CC 16
#define HH 32
#define WW 512
#define NS 9   // shifts: off = s - 4, s in [0,8]

// Scratch (allocation-free): per (pair, batch, shift) accumulators.
__device__ float g_num[2][BB][NS];
__device__ float g_cnt[2][BB][NS];
__device__ int   g_mask_mode;   // 0 = uint8, 1 = int32, 2 = float32

// ---------------------------------------------------------------------------
// Prep: zero accumulators + detect mask dtype from raw bytes (deterministic).
// ---------------------------------------------------------------------------
__global__ void prep_kernel(const unsigned int* __restrict__ mwords) {
    int t = threadIdx.x;
    float* gn = &g_num[0][0][0];
    float* gc = &g_cnt[0][0][0];
    for (int i = t; i < 2 * BB * NS; i += blockDim.x) { gn[i] = 0.f; gc[i] = 0.f; }
    if (t == 0) {
        bool anyf = false, anybig = false;
        for (int i = 0; i < 256; i++) {
            unsigned int w = mwords[i];
            if (w == 0x3F800000u) anyf = true;          // fp32 1.0 pattern
            else if (w >> 8)      anybig = true;        // impossible for i32 bool
        }
        // u8 masks (p=0.8 ones) virtually always produce upper-byte-set words.
        g_mask_mode = anyf ? 2 : (anybig ? 0 : 1);
    }
}

__device__ __forceinline__ void load_mask4(const char* m, size_t base, int mode,
                                           bool out[4]) {
    if (mode == 0) {
        uchar4 v = *reinterpret_cast<const uchar4*>(m + base);
        out[0] = v.x != 0; out[1] = v.y != 0; out[2] = v.z != 0; out[3] = v.w != 0;
    } else if (mode == 1) {
        const int* p = reinterpret_cast<const int*>(m) + base;
        out[0] = p[0] != 0; out[1] = p[1] != 0; out[2] = p[2] != 0; out[3] = p[3] != 0;
    } else {
        const float* p = reinterpret_cast<const float*>(m) + base;
        out[0] = p[0] != 0.f; out[1] = p[1] != 0.f; out[2] = p[2] != 0.f; out[3] = p[3] != 0.f;
    }
}

// ---------------------------------------------------------------------------
// Main kernel: one CTA per (b,h). 128 threads, 4 consecutive w per thread.
// Uses Sa + Sf - 2X decomposition; masks applied only at (w,shift) level.
// ---------------------------------------------------------------------------
__global__ void __launch_bounds__(128, 3) loss_kernel(
    const float* __restrict__ A, const float* __restrict__ P,
    const float* __restrict__ Nt,
    const char* __restrict__ MA, const char* __restrict__ MP,
    const char* __restrict__ MN)
{
    __shared__ float         sf[CC][WW];   // 32 KB: current f (p or n) row
    __shared__ float         sSb[WW];      // per-w sum over c of f^2
    __shared__ unsigned char smk[WW];      // f mask row

    const int t  = threadIdx.x;
    const int b  = blockIdx.x >> 5;
    const int h  = blockIdx.x & 31;
    const int mode = g_mask_mode;
    const int w0 = t * 4;
    const int e0 = (w0 - 4) & (WW - 1);
    const int e2 = (w0 + 4) & (WW - 1);

    const size_t row_off = ((size_t)b * CC * HH + h) * WW;   // + c*HH*WW + w
    const size_t mrow    = ((size_t)b * HH + h) * WW;

    // a row -> registers (reused for both pairs), plus Sa = sum_c a^2
    float4 av[CC];
    float Sa[4] = {0.f, 0.f, 0.f, 0.f};
#pragma unroll
    for (int c = 0; c < CC; c++) {
        float4 v = *reinterpret_cast<const float4*>(A + row_off + (size_t)c * HH * WW + w0);
        av[c] = v;
        Sa[0] = fmaf(v.x, v.x, Sa[0]);
        Sa[1] = fmaf(v.y, v.y, Sa[1]);
        Sa[2] = fmaf(v.z, v.z, Sa[2]);
        Sa[3] = fmaf(v.w, v.w, Sa[3]);
    }
    bool mam[4];
    load_mask4(MA, mode == 0 ? (mrow + w0) : (mrow + w0), mode, mam);

    const float* Fp[2] = {P, Nt};
    const char*  Mp[2] = {MP, MN};

    for (int pair = 0; pair < 2; pair++) {
        const float* F  = Fp[pair];
        const char*  MF = Mp[pair];

        // Stage f row into smem; compute Sb per w on the fly.
        float sb[4] = {0.f, 0.f, 0.f, 0.f};
#pragma unroll
        for (int c = 0; c < CC; c++) {
            float4 v = *reinterpret_cast<const float4*>(F + row_off + (size_t)c * HH * WW + w0);
            *reinterpret_cast<float4*>(&sf[c][w0]) = v;
            sb[0] = fmaf(v.x, v.x, sb[0]);
            sb[1] = fmaf(v.y, v.y, sb[1]);
            sb[2] = fmaf(v.z, v.z, sb[2]);
            sb[3] = fmaf(v.w, v.w, sb[3]);
        }
        *reinterpret_cast<float4*>(&sSb[w0]) = make_float4(sb[0], sb[1], sb[2], sb[3]);
        {
            bool mf[4];
            load_mask4(MF, mrow + w0, mode, mf);
            smk[w0 + 0] = mf[0]; smk[w0 + 1] = mf[1];
            smk[w0 + 2] = mf[2]; smk[w0 + 3] = mf[3];
        }
        __syncthreads();

        // Cross-correlation X[j][s] = sum_c a[c][w0+j] * f[c][w0+j - off], off = s-4
        float X[4 * NS];
#pragma unroll
        for (int i = 0; i < 4 * NS; i++) X[i] = 0.f;

#pragma unroll
        for (int c = 0; c < CC; c++) {
            float4 W0 = *reinterpret_cast<const float4*>(&sf[c][e0]);
            float4 W1 = *reinterpret_cast<const float4*>(&sf[c][w0]);
            float4 W2 = *reinterpret_cast<const float4*>(&sf[c][e2]);
            float win[12] = {W0.x, W0.y, W0.z, W0.w,
                             W1.x, W1.y, W1.z, W1.w,
                             W2.x, W2.y, W2.z, W2.w};
            float aj[4] = {av[c].x, av[c].y, av[c].z, av[c].w};
#pragma unroll
            for (int j = 0; j < 4; j++)
#pragma unroll
                for (int s = 0; s < NS; s++)
                    X[j * NS + s] = fmaf(aj[j], win[j + 8 - s], X[j * NS + s]);
        }

        // Combine with Sb window + mask window, accumulate per-shift num/cnt.
        float4 S0 = *reinterpret_cast<const float4*>(&sSb[e0]);
        float4 S1 = *reinterpret_cast<const float4*>(&sSb[w0]);
        float4 S2 = *reinterpret_cast<const float4*>(&sSb[e2]);
        float swin[12] = {S0.x, S0.y, S0.z, S0.w,
                          S1.x, S1.y, S1.z, S1.w,
                          S2.x, S2.y, S2.z, S2.w};
        uchar4 M0 = *reinterpret_cast<const uchar4*>(&smk[e0]);
        uchar4 M1 = *reinterpret_cast<const uchar4*>(&smk[w0]);
        uchar4 M2 = *reinterpret_cast<const uchar4*>(&smk[e2]);
        unsigned char mwin[12] = {M0.x, M0.y, M0.z, M0.w,
                                  M1.x, M1.y, M1.z, M1.w,
                                  M2.x, M2.y, M2.z, M2.w};

        float num[NS], cnt[NS];
#pragma unroll
        for (int s = 0; s < NS; s++) { num[s] = 0.f; cnt[s] = 0.f; }

#pragma unroll
        for (int j = 0; j < 4; j++)
#pragma unroll
            for (int s = 0; s < NS; s++) {
                const int idx = j + 8 - s;
                float v = fmaf(-2.f, X[j * NS + s], Sa[j]) + swin[idx];
                if (mam[j] && (mwin[idx] != 0)) {
                    num[s] += v;
                    cnt[s] += 1.f;
                }
            }

        // Warp-level reduce then one atomic per (warp, shift).
#pragma unroll
        for (int s = 0; s < NS; s++) {
            float vn = num[s], vc = cnt[s];
            for (int o = 16; o > 0; o >>= 1) {
                vn += __shfl_down_sync(0xffffffffu, vn, o);
                vc += __shfl_down_sync(0xffffffffu, vc, o);
            }
            if ((t & 31) == 0) {
                atomicAdd(&g_num[pair][b][s], vn);
                atomicAdd(&g_cnt[pair][b][s], vc);
            }
        }
        __syncthreads();   // smem reuse barrier before next pair
    }
}

// ---------------------------------------------------------------------------
// Finalize: per-b min over shifts, relu-margin, mean over B -> scalar.
// ---------------------------------------------------------------------------
__global__ void finalize_kernel(float* __restrict__ out) {
    __shared__ float red[BB];
    int b = threadIdx.x;   // 64 threads
    float lap = 1e30f, lan = 1e30f;
#pragma unroll
    for (int s = 0; s < NS; s++) {
        lap = fminf(lap, g_num[0][b][s] / (16.f * g_cnt[0][b][s] + 0.001f));
        lan = fminf(lan, g_num[1][b][s] / (16.f * g_cnt[1][b][s] + 0.001f));
    }
    red[b] = fmaxf(lap - lan + 0.15f, 0.f);
    __syncthreads();
    for (int o = 32; o > 0; o >>= 1) {
        if (b < o) red[b] += red[b + o];
        __syncthreads();
    }
    if (b == 0) out[0] = red[0] / (float)BB;
}

// ---------------------------------------------------------------------------
extern "C" void kernel_launch(void* const* d_in, const int* in_sizes, int n_in,
                              void* d_out, int out_size) {
    const float* A  = (const float*)d_in[0];
    const float* P  = (const float*)d_in[1];
    const float* Nt = (const float*)d_in[2];
    const char*  MA = (const char*)d_in[3];
    const char*  MP = (const char*)d_in[4];
    const char*  MN = (const char*)d_in[5];
    float* out = (float*)d_out;

    prep_kernel<<<1, 256>>>((const unsigned int*)MA);
    loss_kernel<<<BB * HH, 128>>>(A, P, Nt, MA, MP, MN);
    finalize_kernel<<<1, BB>>>(out);
}

// round 2
// speedup vs baseline: 1.8336x; 1.8336x over previous
#include <cuda_runtime.h>

#define BB 64
#define CC 16
#define HH 32
#define WW 512
#define NS 9   // shifts: off = s - 4, s in [0,8]

// Scratch (allocation-free): per (pair, batch, shift) accumulators.
__device__ float g_num[2][BB][NS];
__device__ float g_cnt[2][BB][NS];
__device__ int   g_mask_mode;   // 0 = uint8, 1 = int32, 2 = float32

// ---------------------------------------------------------------------------
// Prep: zero accumulators + parallel mask-dtype sniff (deterministic).
// ---------------------------------------------------------------------------
__global__ void prep_kernel(const unsigned int* __restrict__ mwords) {
    __shared__ int flags[2];   // [0]=saw f32 1.0 word, [1]=saw word with high bytes
    int t = threadIdx.x;
    if (t < 2) flags[t] = 0;
    float* gn = &g_num[0][0][0];
    float* gc = &g_cnt[0][0][0];
    for (int i = t; i < 2 * BB * NS; i += blockDim.x) { gn[i] = 0.f; gc[i] = 0.f; }
    __syncthreads();
    unsigned int w = mwords[t];          // 256 threads, one word each
    if (w == 0x3F800000u)      atomicOr(&flags[0], 1);
    else if (w >> 8)           atomicOr(&flags[1], 1);
    __syncthreads();
    if (t == 0) g_mask_mode = flags[0] ? 2 : (flags[1] ? 0 : 1);
}

__device__ __forceinline__ void load_mask4f(const char* __restrict__ m, size_t base,
                                            int mode, float out[4]) {
    if (mode == 0) {
        uchar4 v = *reinterpret_cast<const uchar4*>(m + base);
        out[0] = v.x ? 1.f : 0.f; out[1] = v.y ? 1.f : 0.f;
        out[2] = v.z ? 1.f : 0.f; out[3] = v.w ? 1.f : 0.f;
    } else if (mode == 1) {
        int4 v = *reinterpret_cast<const int4*>(reinterpret_cast<const int*>(m) + base);
        out[0] = v.x ? 1.f : 0.f; out[1] = v.y ? 1.f : 0.f;
        out[2] = v.z ? 1.f : 0.f; out[3] = v.w ? 1.f : 0.f;
    } else {
        float4 v = *reinterpret_cast<const float4*>(reinterpret_cast<const float*>(m) + base);
        out[0] = v.x != 0.f ? 1.f : 0.f; out[1] = v.y != 0.f ? 1.f : 0.f;
        out[2] = v.z != 0.f ? 1.f : 0.f; out[3] = v.w != 0.f ? 1.f : 0.f;
    }
}

__device__ __forceinline__ void cp_async16(unsigned int sdst, const void* gsrc) {
    asm volatile("cp.async.cg.shared.global [%0], [%1], 16;\n" :: "r"(sdst), "l"(gsrc));
}
__device__ __forceinline__ void cp_commit() {
    asm volatile("cp.async.commit_group;\n" ::: "memory");
}
template <int N> __device__ __forceinline__ void cp_wait() {
    asm volatile("cp.async.wait_group %0;\n" :: "n"(N) : "memory");
}

// ---------------------------------------------------------------------------
// Main kernel: one CTA per (b,h). 128 threads, 4 consecutive w per thread.
// cp.async double-buffers the p/n rows; a row lives in registers.
// ---------------------------------------------------------------------------
__global__ void __launch_bounds__(128, 3) loss_kernel(
    const float* __restrict__ A, const float* __restrict__ P,
    const float* __restrict__ Nt,
    const char* __restrict__ MA, const char* __restrict__ MP,
    const char* __restrict__ MN)
{
    extern __shared__ float smem[];
    float* sf  = smem;                 // [2][CC][WW]  64 KB
    float* sSb = sf + 2 * CC * WW;     // [WW]          2 KB
    float* smk = sSb + WW;             // [WW]          2 KB

    const int t  = threadIdx.x;
    const int b  = blockIdx.x >> 5;
    const int h  = blockIdx.x & 31;
    const int mode = g_mask_mode;
    const int w0 = t * 4;
    const int e0 = (w0 - 4) & (WW - 1);
    const int e2 = (w0 + 4) & (WW - 1);

    const size_t row_off = ((size_t)b * CC * HH + h) * WW;   // + c*HH*WW + w
    const size_t mrow    = ((size_t)b * HH + h) * WW;

    // Issue cp.async for P row -> buffer 0  (group depth 2 after N issued)
#pragma unroll
    for (int c = 0; c < CC; c++)
        cp_async16((unsigned int)__cvta_generic_to_shared(&sf[(0 * CC + c) * WW + w0]),
                   P + row_off + (size_t)c * HH * WW + w0);
    cp_commit();

    // a row -> registers, plus Sa = sum_c a^2  (LDGs overlap with cp.asyncs)
    float4 av[CC];
    float Sa[4] = {0.f, 0.f, 0.f, 0.f};
#pragma unroll
    for (int c = 0; c < CC; c++) {
        float4 v = *reinterpret_cast<const float4*>(A + row_off + (size_t)c * HH * WW + w0);
        av[c] = v;
        Sa[0] = fmaf(v.x, v.x, Sa[0]);
        Sa[1] = fmaf(v.y, v.y, Sa[1]);
        Sa[2] = fmaf(v.z, v.z, Sa[2]);
        Sa[3] = fmaf(v.w, v.w, Sa[3]);
    }

    // Issue cp.async for N row -> buffer 1
#pragma unroll
    for (int c = 0; c < CC; c++)
        cp_async16((unsigned int)__cvta_generic_to_shared(&sf[(1 * CC + c) * WW + w0]),
                   Nt + row_off + (size_t)c * HH * WW + w0);
    cp_commit();

    // Mask rows (tiny): all three up front as 0/1 floats in registers.
    float mam[4], mfv[2][4];
    load_mask4f(MA, mrow + w0, mode, mam);
    load_mask4f(MP, mrow + w0, mode, mfv[0]);
    load_mask4f(MN, mrow + w0, mode, mfv[1]);

#pragma unroll
    for (int pair = 0; pair < 2; pair++) {
        if (pair == 0) cp_wait<1>(); else cp_wait<0>();
        __syncthreads();   // buffer visible to all threads

        const float* fb = &sf[pair * CC * WW];

        // Sb per w (from smem) + mask row to smem.
        float sb[4] = {0.f, 0.f, 0.f, 0.f};
#pragma unroll
        for (int c = 0; c < CC; c++) {
            float4 v = *reinterpret_cast<const float4*>(&fb[c * WW + w0]);
            sb[0] = fmaf(v.x, v.x, sb[0]);
            sb[1] = fmaf(v.y, v.y, sb[1]);
            sb[2] = fmaf(v.z, v.z, sb[2]);
            sb[3] = fmaf(v.w, v.w, sb[3]);
        }
        *reinterpret_cast<float4*>(&sSb[w0]) = make_float4(sb[0], sb[1], sb[2], sb[3]);
        *reinterpret_cast<float4*>(&smk[w0]) =
            make_float4(mfv[pair][0], mfv[pair][1], mfv[pair][2], mfv[pair][3]);
        __syncthreads();

        // Cross-correlation X[j][s] = sum_c a[c][w0+j] * f[c][w0+j-off], off = s-4
        float X[4 * NS];
#pragma unroll
        for (int i = 0; i < 4 * NS; i++) X[i] = 0.f;

#pragma unroll
        for (int c = 0; c < CC; c++) {
            float4 W0 = *reinterpret_cast<const float4*>(&fb[c * WW + e0]);
            float4 W1 = *reinterpret_cast<const float4*>(&fb[c * WW + w0]);
            float4 W2 = *reinterpret_cast<const float4*>(&fb[c * WW + e2]);
            float win[12] = {W0.x, W0.y, W0.z, W0.w,
                             W1.x, W1.y, W1.z, W1.w,
                             W2.x, W2.y, W2.z, W2.w};
            float aj[4] = {av[c].x, av[c].y, av[c].z, av[c].w};
#pragma unroll
            for (int j = 0; j < 4; j++)
#pragma unroll
                for (int s = 0; s < NS; s++)
                    X[j * NS + s] = fmaf(aj[j], win[j + 8 - s], X[j * NS + s]);
        }

        // Combine with Sb + mask windows, branch-free.
        float4 S0 = *reinterpret_cast<const float4*>(&sSb[e0]);
        float4 S1 = *reinterpret_cast<const float4*>(&sSb[w0]);
        float4 S2 = *reinterpret_cast<const float4*>(&sSb[e2]);
        float swin[12] = {S0.x, S0.y, S0.z, S0.w,
                          S1.x, S1.y, S1.z, S1.w,
                          S2.x, S2.y, S2.z, S2.w};
        float4 M0 = *reinterpret_cast<const float4*>(&smk[e0]);
        float4 M1 = *reinterpret_cast<const float4*>(&smk[w0]);
        float4 M2 = *reinterpret_cast<const float4*>(&smk[e2]);
        float mwin[12] = {M0.x, M0.y, M0.z, M0.w,
                          M1.x, M1.y, M1.z, M1.w,
                          M2.x, M2.y, M2.z, M2.w};

        float num[NS], cnt[NS];
#pragma unroll
        for (int s = 0; s < NS; s++) { num[s] = 0.f; cnt[s] = 0.f; }

#pragma unroll
        for (int j = 0; j < 4; j++)
#pragma unroll
            for (int s = 0; s < NS; s++) {
                const int idx = j + 8 - s;
                float v  = fmaf(-2.f, X[j * NS + s], Sa[j]) + swin[idx];
                float mm = mam[j] * mwin[idx];
                num[s] = fmaf(mm, v, num[s]);
                cnt[s] += mm;
            }

        // Warp-level reduce then one atomic per (warp, shift).
#pragma unroll
        for (int s = 0; s < NS; s++) {
            float vn = num[s], vc = cnt[s];
            for (int o = 16; o > 0; o >>= 1) {
                vn += __shfl_down_sync(0xffffffffu, vn, o);
                vc += __shfl_down_sync(0xffffffffu, vc, o);
            }
            if ((t & 31) == 0) {
                atomicAdd(&g_num[pair][b][s], vn);
                atomicAdd(&g_cnt[pair][b][s], vc);
            }
        }
        __syncthreads();   // smem (sSb/smk) reuse barrier before next pair
    }
}

// ---------------------------------------------------------------------------
// Finalize: per-b min over shifts, relu-margin, mean over B -> scalar.
// ---------------------------------------------------------------------------
__global__ void finalize_kernel(float* __restrict__ out) {
    __shared__ float red[BB];
    int b = threadIdx.x;   // 64 threads
    float lap = 1e30f, lan = 1e30f;
#pragma unroll
    for (int s = 0; s < NS; s++) {
        lap = fminf(lap, g_num[0][b][s] / (16.f * g_cnt[0][b][s] + 0.001f));
        lan = fminf(lan, g_num[1][b][s] / (16.f * g_cnt[1][b][s] + 0.001f));
    }
    red[b] = fmaxf(lap - lan + 0.15f, 0.f);
    __syncthreads();
    for (int o = 32; o > 0; o >>= 1) {
        if (b < o) red[b] += red[b + o];
        __syncthreads();
    }
    if (b == 0) out[0] = red[0] / (float)BB;
}

// ---------------------------------------------------------------------------
extern "C" void kernel_launch(void* const* d_in, const int* in_sizes, int n_in,
                              void* d_out, int out_size) {
    const float* A  = (const float*)d_in[0];
    const float* P  = (const float*)d_in[1];
    const float* Nt = (const float*)d_in[2];
    const char*  MA = (const char*)d_in[3];
    const char*  MP = (const char*)d_in[4];
    const char*  MN = (const char*)d_in[5];
    float* out = (float*)d_out;

    const int smem_bytes = (2 * CC * WW + 2 * WW) * (int)sizeof(float);  // 68 KB
    cudaFuncSetAttribute(loss_kernel, cudaFuncAttributeMaxDynamicSharedMemorySize,
                         smem_bytes);

    prep_kernel<<<1, 256>>>((const unsigned int*)MA);
    loss_kernel<<<BB * HH, 128, smem_bytes>>>(A, P, Nt, MA, MP, MN);
    finalize_kernel<<<1, BB>>>(out);
}

// round 3
// speedup vs baseline: 2.0312x; 1.1078x over previous
#include <cuda_runtime.h>

#define BB 64
#define CC 16
#define HH 32
#define WW 512
#define NS 9    // shifts: off = s - 4
#define CT 4    // channels per cp.async tile
#define NBUF 4  // ring buffers

// Per-(pair,b,s,h) partials — pure writes, no zeroing / atomics needed.
__device__ float g_pnum[2][BB][NS][HH];
__device__ float g_pcnt[2][BB][NS][HH];

__device__ __forceinline__ void cp_async16(unsigned int sdst, const void* gsrc) {
    asm volatile("cp.async.cg.shared.global [%0], [%1], 16;\n" :: "r"(sdst), "l"(gsrc));
}
__device__ __forceinline__ void cp_commit() {
    asm volatile("cp.async.commit_group;\n" ::: "memory");
}
template <int N> __device__ __forceinline__ void cp_wait() {
    asm volatile("cp.async.wait_group %0;\n" :: "n"(N) : "memory");
}

__device__ __forceinline__ void load_mask4f(const char* __restrict__ m, size_t base,
                                            int mode, float out[4]) {
    if (mode == 0) {
        uchar4 v = *reinterpret_cast<const uchar4*>(m + base);
        out[0] = v.x ? 1.f : 0.f; out[1] = v.y ? 1.f : 0.f;
        out[2] = v.z ? 1.f : 0.f; out[3] = v.w ? 1.f : 0.f;
    } else if (mode == 1) {
        int4 v = *reinterpret_cast<const int4*>(reinterpret_cast<const int*>(m) + base);
        out[0] = v.x ? 1.f : 0.f; out[1] = v.y ? 1.f : 0.f;
        out[2] = v.z ? 1.f : 0.f; out[3] = v.w ? 1.f : 0.f;
    } else {
        float4 v = *reinterpret_cast<const float4*>(reinterpret_cast<const float*>(m) + base);
        out[0] = v.x != 0.f ? 1.f : 0.f; out[1] = v.y != 0.f ? 1.f : 0.f;
        out[2] = v.z != 0.f ? 1.f : 0.f; out[3] = v.w != 0.f ? 1.f : 0.f;
    }
}

// ---------------------------------------------------------------------------
// One CTA per (b,h). 128 threads, 4 consecutive w per thread.
// f rows streamed as 8 KB channel-tiles through a depth-3 cp.async ring.
// ---------------------------------------------------------------------------
__global__ void __launch_bounds__(128, 4) loss_kernel(
    const float* __restrict__ A, const float* __restrict__ P,
    const float* __restrict__ Nt,
    const char* __restrict__ MA, const char* __restrict__ MP,
    const char* __restrict__ MN)
{
    __shared__ __align__(16) float ring[NBUF][CT][WW];   // 32 KB
    __shared__ __align__(16) float sSb[WW];              // 2 KB
    __shared__ __align__(16) float smA[WW];              // 2 KB (a mask as 0/1 f32)
    __shared__ __align__(16) float smF[2][WW];           // 4 KB (p/n masks)
    __shared__ float red_n[2][NS][4], red_c[2][NS][4];
    __shared__ unsigned int sflag[4];                    // f32 ballots, big-byte ballots

    const int t  = threadIdx.x;
    const int b  = blockIdx.x >> 5;
    const int h  = blockIdx.x & 31;
    const int w0 = t * 4;
    const int e0 = (w0 - 4) & (WW - 1);
    const int e2 = (w0 + 4) & (WW - 1);

    const size_t row_off = ((size_t)b * CC * HH + h) * WW;
    const size_t mrow    = ((size_t)b * HH + h) * WW;

    // -- mask dtype sniff (identical, deterministic result in every CTA) ----
    if (t < 64) {
        unsigned int w = reinterpret_cast<const unsigned int*>(MA)[t];
        unsigned int bf = __ballot_sync(0xffffffffu, w == 0x3F800000u);
        unsigned int bg = __ballot_sync(0xffffffffu, (w >> 8) != 0u);
        if ((t & 31) == 0) { sflag[t >> 5] = bf; sflag[2 + (t >> 5)] = bg; }
    }

    // -- start the f-tile stream (tiles 0..2) -------------------------------
    auto issue_tile = [&](int k) {
        const float* F = (k >= 4) ? Nt : P;
        const int ct = k & 3, buf = k & 3;
#pragma unroll
        for (int cc = 0; cc < CT; cc++)
            cp_async16((unsigned int)__cvta_generic_to_shared(&ring[buf][cc][w0]),
                       F + row_off + (size_t)(ct * CT + cc) * HH * WW + w0);
        cp_commit();
    };
    issue_tile(0); issue_tile(1); issue_tile(2);
    __syncthreads();
    const int mode = (sflag[0] | sflag[1]) ? 2 : ((sflag[2] | sflag[3]) ? 0 : 1);

    // -- a row -> registers + Sa -------------------------------------------
    float4 av[CC];
    float Sa[4] = {0.f, 0.f, 0.f, 0.f};
#pragma unroll
    for (int c = 0; c < CC; c++) {
        float4 v = *reinterpret_cast<const float4*>(A + row_off + (size_t)c * HH * WW + w0);
        av[c] = v;
        Sa[0] = fmaf(v.x, v.x, Sa[0]);
        Sa[1] = fmaf(v.y, v.y, Sa[1]);
        Sa[2] = fmaf(v.z, v.z, Sa[2]);
        Sa[3] = fmaf(v.w, v.w, Sa[3]);
    }

    // -- masks -> smem as 0/1 floats ---------------------------------------
    {
        float m4[4];
        load_mask4f(MA, mrow + w0, mode, m4);
        *reinterpret_cast<float4*>(&smA[w0]) = make_float4(m4[0], m4[1], m4[2], m4[3]);
        load_mask4f(MP, mrow + w0, mode, m4);
        *reinterpret_cast<float4*>(&smF[0][w0]) = make_float4(m4[0], m4[1], m4[2], m4[3]);
        load_mask4f(MN, mrow + w0, mode, m4);
        *reinterpret_cast<float4*>(&smF[1][w0]) = make_float4(m4[0], m4[1], m4[2], m4[3]);
    }

    float X[4 * NS];
#pragma unroll
    for (int i = 0; i < 4 * NS; i++) X[i] = 0.f;
    float sb[4] = {0.f, 0.f, 0.f, 0.f};

    // -- main tile loop: 8 tiles = (P tiles 0..3, N tiles 0..3) -------------
#pragma unroll
    for (int k = 0; k < 8; k++) {
        if (k <= 5)      cp_wait<2>();
        else if (k == 6) cp_wait<1>();
        else             cp_wait<0>();
        __syncthreads();                 // tile k visible; buf (k-1)%4 free
        if (k < 5) issue_tile(k + 3);

        const int pair = k >> 2, ct = k & 3, buf = k & 3;

#pragma unroll
        for (int cc = 0; cc < CT; cc++) {
            const int c = ct * CT + cc;
            float4 W0 = *reinterpret_cast<const float4*>(&ring[buf][cc][e0]);
            float4 W1 = *reinterpret_cast<const float4*>(&ring[buf][cc][w0]);
            float4 W2 = *reinterpret_cast<const float4*>(&ring[buf][cc][e2]);
            sb[0] = fmaf(W1.x, W1.x, sb[0]);
            sb[1] = fmaf(W1.y, W1.y, sb[1]);
            sb[2] = fmaf(W1.z, W1.z, sb[2]);
            sb[3] = fmaf(W1.w, W1.w, sb[3]);
            float win[12] = {W0.x, W0.y, W0.z, W0.w,
                             W1.x, W1.y, W1.z, W1.w,
                             W2.x, W2.y, W2.z, W2.w};
            float aj[4] = {av[c].x, av[c].y, av[c].z, av[c].w};
#pragma unroll
            for (int j = 0; j < 4; j++)
#pragma unroll
                for (int s = 0; s < NS; s++)
                    X[j * NS + s] = fmaf(aj[j], win[j + 8 - s], X[j * NS + s]);
        }

        if (ct == 3) {   // pair epilogue
            *reinterpret_cast<float4*>(&sSb[w0]) = make_float4(sb[0], sb[1], sb[2], sb[3]);
            __syncthreads();

            float4 S0 = *reinterpret_cast<const float4*>(&sSb[e0]);
            float4 S1 = *reinterpret_cast<const float4*>(&sSb[w0]);
            float4 S2 = *reinterpret_cast<const float4*>(&sSb[e2]);
            float swin[12] = {S0.x, S0.y, S0.z, S0.w,
                              S1.x, S1.y, S1.z, S1.w,
                              S2.x, S2.y, S2.z, S2.w};
            float4 M0 = *reinterpret_cast<const float4*>(&smF[pair][e0]);
            float4 M1 = *reinterpret_cast<const float4*>(&smF[pair][w0]);
            float4 M2 = *reinterpret_cast<const float4*>(&smF[pair][e2]);
            float mwin[12] = {M0.x, M0.y, M0.z, M0.w,
                              M1.x, M1.y, M1.z, M1.w,
                              M2.x, M2.y, M2.z, M2.w};
            float4 ma4 = *reinterpret_cast<const float4*>(&smA[w0]);
            float mam[4] = {ma4.x, ma4.y, ma4.z, ma4.w};

            float num[NS], cnt[NS];
#pragma unroll
            for (int s = 0; s < NS; s++) { num[s] = 0.f; cnt[s] = 0.f; }
#pragma unroll
            for (int j = 0; j < 4; j++)
#pragma unroll
                for (int s = 0; s < NS; s++) {
                    const int idx = j + 8 - s;
                    float v  = fmaf(-2.f, X[j * NS + s], Sa[j]) + swin[idx];
                    float mm = mam[j] * mwin[idx];
                    num[s] = fmaf(mm, v, num[s]);
                    cnt[s] += mm;
                }

#pragma unroll
            for (int s = 0; s < NS; s++) {
                float vn = num[s], vc = cnt[s];
                for (int o = 16; o > 0; o >>= 1) {
                    vn += __shfl_down_sync(0xffffffffu, vn, o);
                    vc += __shfl_down_sync(0xffffffffu, vc, o);
                }
                if ((t & 31) == 0) {
                    red_n[pair][s][t >> 5] = vn;
                    red_c[pair][s][t >> 5] = vc;
                }
            }

#pragma unroll
            for (int i = 0; i < 4 * NS; i++) X[i] = 0.f;
            sb[0] = sb[1] = sb[2] = sb[3] = 0.f;
        }
    }

    __syncthreads();
    if (t < 36) {   // write per-(b,h) partial slots (no atomics)
        const int pair = (t % 18) / 9, s = t % 9;
        if (t < 18) {
            float v = red_n[pair][s][0] + red_n[pair][s][1] +
                      red_n[pair][s][2] + red_n[pair][s][3];
            g_pnum[pair][b][s][h] = v;
        } else {
            float v = red_c[pair][s][0] + red_c[pair][s][1] +
                      red_c[pair][s][2] + red_c[pair][s][3];
            g_pcnt[pair][b][s][h] = v;
        }
    }
}

// ---------------------------------------------------------------------------
// Finalize: reduce partials over h, min over shifts, relu-margin, mean.
// ---------------------------------------------------------------------------
__global__ void finalize_kernel(float* __restrict__ out) {
    __shared__ float s_num[2 * BB * NS];
    __shared__ float s_cnt[2 * BB * NS];
    __shared__ float red[BB];
    const int t = threadIdx.x;   // 512

    for (int i = t; i < 2 * BB * NS; i += 512) {
        const float* pn = &g_pnum[0][0][0][0] + (size_t)i * HH;
        const float* pc = &g_pcnt[0][0][0][0] + (size_t)i * HH;
        float sn = 0.f, sc = 0.f;
#pragma unroll
        for (int hh = 0; hh < HH; hh += 4) {
            float4 v = *reinterpret_cast<const float4*>(pn + hh);
            float4 u = *reinterpret_cast<const float4*>(pc + hh);
            sn += (v.x + v.y) + (v.z + v.w);
            sc += (u.x + u.y) + (u.z + u.w);
        }
        s_num[i] = sn; s_cnt[i] = sc;
    }
    __syncthreads();

    if (t < BB) {
        float lap = 1e30f, lan = 1e30f;
#pragma unroll
        for (int s = 0; s < NS; s++) {
            lap = fminf(lap, s_num[(0 * BB + t) * NS + s] /
                             (16.f * s_cnt[(0 * BB + t) * NS + s] + 0.001f));
            lan = fminf(lan, s_num[(1 * BB + t) * NS + s] /
                             (16.f * s_cnt[(1 * BB + t) * NS + s] + 0.001f));
        }
        red[t] = fmaxf(lap - lan + 0.15f, 0.f);
    }
    __syncthreads();
    for (int o = 32; o > 0; o >>= 1) {
        if (t < o && t + o < BB) red[t] += red[t + o];
        __syncthreads();
    }
    if (t == 0) out[0] = red[0] / (float)BB;
}

// ---------------------------------------------------------------------------
extern "C" void kernel_launch(void* const* d_in, const int* in_sizes, int n_in,
                              void* d_out, int out_size) {
    const float* A  = (const float*)d_in[0];
    const float* P  = (const float*)d_in[1];
    const float* Nt = (const float*)d_in[2];
    const char*  MA = (const char*)d_in[3];
    const char*  MP = (const char*)d_in[4];
    const char*  MN = (const char*)d_in[5];
    float* out = (float*)d_out;

    loss_kernel<<<BB * HH, 128>>>(A, P, Nt, MA, MP, MN);
    finalize_kernel<<<1, 512>>>(out);
}

// round 4
// speedup vs baseline: 2.5996x; 1.2798x over previous
#include <cuda_runtime.h>

#define BB 64
#define CC 16
#define HH 32
#define WW 512
#define NS 9    // shifts: off = s - 4
#define CT 4    // channels per cp.async tile
#define NBUF 4  // ring buffers

// Per-(pair,b,s,h) partials — pure writes, no zeroing / atomics needed.
__device__ float g_pnum[2][BB][NS][HH];
__device__ float g_pcnt[2][BB][NS][HH];
__device__ float g_bloss[BB];

typedef unsigned long long ull;

__device__ __forceinline__ void cp_async16(unsigned int sdst, const void* gsrc) {
    asm volatile("cp.async.cg.shared.global [%0], [%1], 16;\n" :: "r"(sdst), "l"(gsrc));
}
__device__ __forceinline__ void cp_commit() {
    asm volatile("cp.async.commit_group;\n" ::: "memory");
}
template <int N> __device__ __forceinline__ void cp_wait() {
    asm volatile("cp.async.wait_group %0;\n" :: "n"(N) : "memory");
}

// Packed fp32x2 helpers (sm_103a FFMA2 — PTX only)
__device__ __forceinline__ ull pk2(float lo, float hi) {
    ull r; asm("mov.b64 %0, {%1, %2};" : "=l"(r) : "f"(lo), "f"(hi)); return r;
}
__device__ __forceinline__ float2 upk(ull v) {
    float2 f; asm("mov.b64 {%0, %1}, %2;" : "=f"(f.x), "=f"(f.y) : "l"(v)); return f;
}
__device__ __forceinline__ void ffma2(ull& d, ull a, ull b) {
    asm("fma.rn.f32x2 %0, %1, %2, %0;" : "+l"(d) : "l"(a), "l"(b));
}

__device__ __forceinline__ void load_mask4f(const char* __restrict__ m, size_t base,
                                            int mode, float out[4]) {
    if (mode == 0) {
        uchar4 v = *reinterpret_cast<const uchar4*>(m + base);
        out[0] = v.x ? 1.f : 0.f; out[1] = v.y ? 1.f : 0.f;
        out[2] = v.z ? 1.f : 0.f; out[3] = v.w ? 1.f : 0.f;
    } else if (mode == 1) {
        int4 v = *reinterpret_cast<const int4*>(reinterpret_cast<const int*>(m) + base);
        out[0] = v.x ? 1.f : 0.f; out[1] = v.y ? 1.f : 0.f;
        out[2] = v.z ? 1.f : 0.f; out[3] = v.w ? 1.f : 0.f;
    } else {
        float4 v = *reinterpret_cast<const float4*>(reinterpret_cast<const float*>(m) + base);
        out[0] = v.x != 0.f ? 1.f : 0.f; out[1] = v.y != 0.f ? 1.f : 0.f;
        out[2] = v.z != 0.f ? 1.f : 0.f; out[3] = v.w != 0.f ? 1.f : 0.f;
    }
}

// ---------------------------------------------------------------------------
// One CTA per (b,h). 128 threads, 4 consecutive w per thread.
// f rows streamed as 8 KB channel-tiles through a depth-3 cp.async ring.
// X cross-correlation uses packed fp32x2 FMA along the j dimension.
// ---------------------------------------------------------------------------
__global__ void __launch_bounds__(128, 4) loss_kernel(
    const float* __restrict__ A, const float* __restrict__ P,
    const float* __restrict__ Nt,
    const char* __restrict__ MA, const char* __restrict__ MP,
    const char* __restrict__ MN)
{
    __shared__ __align__(16) float ring[NBUF][CT][WW];   // 32 KB
    __shared__ __align__(16) float sSb[WW];              // 2 KB
    __shared__ __align__(16) float smA[WW];              // 2 KB
    __shared__ __align__(16) float smF[2][WW];           // 4 KB
    __shared__ float red_n[2][NS][4], red_c[2][NS][4];
    __shared__ unsigned int sflag[4];

    const int t  = threadIdx.x;
    const int b  = blockIdx.x >> 5;
    const int h  = blockIdx.x & 31;
    const int w0 = t * 4;
    const int e0 = (w0 - 4) & (WW - 1);
    const int e2 = (w0 + 4) & (WW - 1);

    const size_t row_off = ((size_t)b * CC * HH + h) * WW;
    const size_t mrow    = ((size_t)b * HH + h) * WW;

    // -- mask dtype sniff (identical deterministic result in every CTA) -----
    if (t < 64) {
        unsigned int w = reinterpret_cast<const unsigned int*>(MA)[t];
        unsigned int bf = __ballot_sync(0xffffffffu, w == 0x3F800000u);
        unsigned int bg = __ballot_sync(0xffffffffu, (w >> 8) != 0u);
        if ((t & 31) == 0) { sflag[t >> 5] = bf; sflag[2 + (t >> 5)] = bg; }
    }

    auto issue_tile = [&](int k) {
        const float* F = (k >= 4) ? Nt : P;
        const int ct = k & 3, buf = k & 3;
#pragma unroll
        for (int cc = 0; cc < CT; cc++)
            cp_async16((unsigned int)__cvta_generic_to_shared(&ring[buf][cc][w0]),
                       F + row_off + (size_t)(ct * CT + cc) * HH * WW + w0);
        cp_commit();
    };
    issue_tile(0); issue_tile(1); issue_tile(2);
    __syncthreads();
    const int mode = (sflag[0] | sflag[1]) ? 2 : ((sflag[2] | sflag[3]) ? 0 : 1);

    // -- a row -> registers + packed Sa ------------------------------------
    float4 av[CC];
    ull Sa2[2] = {pk2(0.f, 0.f), pk2(0.f, 0.f)};
#pragma unroll
    for (int c = 0; c < CC; c++) {
        float4 v = *reinterpret_cast<const float4*>(A + row_off + (size_t)c * HH * WW + w0);
        av[c] = v;
        ull va = pk2(v.x, v.y), vb = pk2(v.z, v.w);
        ffma2(Sa2[0], va, va);
        ffma2(Sa2[1], vb, vb);
    }
    float Sa[4];
    { float2 f = upk(Sa2[0]); Sa[0] = f.x; Sa[1] = f.y;
      f = upk(Sa2[1]);        Sa[2] = f.x; Sa[3] = f.y; }

    // -- masks -> smem as 0/1 floats ---------------------------------------
    {
        float m4[4];
        load_mask4f(MA, mrow + w0, mode, m4);
        *reinterpret_cast<float4*>(&smA[w0]) = make_float4(m4[0], m4[1], m4[2], m4[3]);
        load_mask4f(MP, mrow + w0, mode, m4);
        *reinterpret_cast<float4*>(&smF[0][w0]) = make_float4(m4[0], m4[1], m4[2], m4[3]);
        load_mask4f(MN, mrow + w0, mode, m4);
        *reinterpret_cast<float4*>(&smF[1][w0]) = make_float4(m4[0], m4[1], m4[2], m4[3]);
    }

    // Accumulators: even s packed along j-pairs, odd s scalar.
    ull  X2a[5], X2b[5];           // s = 0,2,4,6,8 : (j0,j1) and (j2,j3)
    float Xo[4][4];                // s = 1,3,5,7   : per-j scalars
    ull  sb2[2];
    const ull z2 = pk2(0.f, 0.f);
#pragma unroll
    for (int m = 0; m < 5; m++) { X2a[m] = z2; X2b[m] = z2; }
#pragma unroll
    for (int j = 0; j < 4; j++)
#pragma unroll
        for (int m = 0; m < 4; m++) Xo[j][m] = 0.f;
    sb2[0] = z2; sb2[1] = z2;

    // -- main tile loop: 8 tiles = (P 0..3, N 0..3) -------------------------
#pragma unroll
    for (int k = 0; k < 8; k++) {
        if (k <= 5)      cp_wait<2>();
        else if (k == 6) cp_wait<1>();
        else             cp_wait<0>();
        __syncthreads();
        if (k < 5) issue_tile(k + 3);

        const int pair = k >> 2, ct = k & 3, buf = k & 3;

#pragma unroll
        for (int cc = 0; cc < CT; cc++) {
            const int c = ct * CT + cc;
            float4 W0 = *reinterpret_cast<const float4*>(&ring[buf][cc][e0]);
            float4 W1 = *reinterpret_cast<const float4*>(&ring[buf][cc][w0]);
            float4 W2 = *reinterpret_cast<const float4*>(&ring[buf][cc][e2]);

            ull wp[6] = {pk2(W0.x, W0.y), pk2(W0.z, W0.w),
                         pk2(W1.x, W1.y), pk2(W1.z, W1.w),
                         pk2(W2.x, W2.y), pk2(W2.z, W2.w)};
            ffma2(sb2[0], wp[2], wp[2]);
            ffma2(sb2[1], wp[3], wp[3]);

            const float win[12] = {W0.x, W0.y, W0.z, W0.w,
                                   W1.x, W1.y, W1.z, W1.w,
                                   W2.x, W2.y, W2.z, W2.w};
            const ull a01 = pk2(av[c].x, av[c].y);
            const ull a23 = pk2(av[c].z, av[c].w);

            // even s = 2m: X[j][s] += a[j] * win[j+8-s]
#pragma unroll
            for (int m = 0; m < 5; m++) {
                ffma2(X2a[m], a01, wp[4 - m]);   // (win[8-2m], win[9-2m])
                ffma2(X2b[m], a23, wp[5 - m]);   // (win[10-2m], win[11-2m])
            }
            // odd s = 2m+1: scalar
#pragma unroll
            for (int m = 0; m < 4; m++) {
                Xo[0][m] = fmaf(av[c].x, win[7 - 2 * m],  Xo[0][m]);
                Xo[1][m] = fmaf(av[c].y, win[8 - 2 * m],  Xo[1][m]);
                Xo[2][m] = fmaf(av[c].z, win[9 - 2 * m],  Xo[2][m]);
                Xo[3][m] = fmaf(av[c].w, win[10 - 2 * m], Xo[3][m]);
            }
        }

        if (ct == 3) {   // pair epilogue
            { float2 f0 = upk(sb2[0]), f1 = upk(sb2[1]);
              *reinterpret_cast<float4*>(&sSb[w0]) = make_float4(f0.x, f0.y, f1.x, f1.y); }
            __syncthreads();

            // Reconstruct X[j][s]
            float X[4][NS];
#pragma unroll
            for (int m = 0; m < 5; m++) {
                float2 fa = upk(X2a[m]), fb = upk(X2b[m]);
                X[0][2 * m] = fa.x; X[1][2 * m] = fa.y;
                X[2][2 * m] = fb.x; X[3][2 * m] = fb.y;
            }
#pragma unroll
            for (int m = 0; m < 4; m++) {
                X[0][2 * m + 1] = Xo[0][m]; X[1][2 * m + 1] = Xo[1][m];
                X[2][2 * m + 1] = Xo[2][m]; X[3][2 * m + 1] = Xo[3][m];
            }

            float4 S0 = *reinterpret_cast<const float4*>(&sSb[e0]);
            float4 S1 = *reinterpret_cast<const float4*>(&sSb[w0]);
            float4 S2 = *reinterpret_cast<const float4*>(&sSb[e2]);
            float swin[12] = {S0.x, S0.y, S0.z, S0.w,
                              S1.x, S1.y, S1.z, S1.w,
                              S2.x, S2.y, S2.z, S2.w};
            float4 M0 = *reinterpret_cast<const float4*>(&smF[pair][e0]);
            float4 M1 = *reinterpret_cast<const float4*>(&smF[pair][w0]);
            float4 M2 = *reinterpret_cast<const float4*>(&smF[pair][e2]);
            float mwin[12] = {M0.x, M0.y, M0.z, M0.w,
                              M1.x, M1.y, M1.z, M1.w,
                              M2.x, M2.y, M2.z, M2.w};
            float4 ma4 = *reinterpret_cast<const float4*>(&smA[w0]);
            float mam[4] = {ma4.x, ma4.y, ma4.z, ma4.w};

            float num[NS], cnt[NS];
#pragma unroll
            for (int s = 0; s < NS; s++) { num[s] = 0.f; cnt[s] = 0.f; }
#pragma unroll
            for (int j = 0; j < 4; j++)
#pragma unroll
                for (int s = 0; s < NS; s++) {
                    const int idx = j + 8 - s;
                    float v  = fmaf(-2.f, X[j][s], Sa[j]) + swin[idx];
                    float mm = mam[j] * mwin[idx];
                    num[s] = fmaf(mm, v, num[s]);
                    cnt[s] += mm;
                }

#pragma unroll
            for (int s = 0; s < NS; s++) {
                float vn = num[s], vc = cnt[s];
                for (int o = 16; o > 0; o >>= 1) {
                    vn += __shfl_down_sync(0xffffffffu, vn, o);
                    vc += __shfl_down_sync(0xffffffffu, vc, o);
                }
                if ((t & 31) == 0) {
                    red_n[pair][s][t >> 5] = vn;
                    red_c[pair][s][t >> 5] = vc;
                }
            }

            // reset accumulators for next pair
#pragma unroll
            for (int m = 0; m < 5; m++) { X2a[m] = z2; X2b[m] = z2; }
#pragma unroll
            for (int j = 0; j < 4; j++)
#pragma unroll
                for (int m = 0; m < 4; m++) Xo[j][m] = 0.f;
            sb2[0] = z2; sb2[1] = z2;
        }
    }

    __syncthreads();
    if (t < 36) {   // per-(b,h) partial slots (no atomics)
        const int pair = (t % 18) / 9, s = t % 9;
        if (t < 18) {
            g_pnum[pair][b][s][h] = red_n[pair][s][0] + red_n[pair][s][1] +
                                    red_n[pair][s][2] + red_n[pair][s][3];
        } else {
            g_pcnt[pair][b][s][h] = red_c[pair][s][0] + red_c[pair][s][1] +
                                    red_c[pair][s][2] + red_c[pair][s][3];
        }
    }
}

// ---------------------------------------------------------------------------
// Per-batch reduce: grid=BB, 9 warps; warp s reduces over h for both pairs.
// ---------------------------------------------------------------------------
__global__ void __launch_bounds__(288) perb_kernel() {
    __shared__ float d[2][NS];
    const int b = blockIdx.x;
    const int wid = threadIdx.x >> 5, lane = threadIdx.x & 31;

    if (wid < NS) {
        float n0 = g_pnum[0][b][wid][lane];
        float c0 = g_pcnt[0][b][wid][lane];
        float n1 = g_pnum[1][b][wid][lane];
        float c1 = g_pcnt[1][b][wid][lane];
#pragma unroll
        for (int o = 16; o > 0; o >>= 1) {
            n0 += __shfl_down_sync(0xffffffffu, n0, o);
            c0 += __shfl_down_sync(0xffffffffu, c0, o);
            n1 += __shfl_down_sync(0xffffffffu, n1, o);
            c1 += __shfl_down_sync(0xffffffffu, c1, o);
        }
        if (lane == 0) {
            d[0][wid] = n0 / (16.f * c0 + 0.001f);
            d[1][wid] = n1 / (16.f * c1 + 0.001f);
        }
    }
    __syncthreads();
    if (threadIdx.x == 0) {
        float lap = d[0][0], lan = d[1][0];
#pragma unroll
        for (int s = 1; s < NS; s++) {
            lap = fminf(lap, d[0][s]);
            lan = fminf(lan, d[1][s]);
        }
        g_bloss[b] = fmaxf(lap - lan + 0.15f, 0.f);
    }
}

// ---------------------------------------------------------------------------
__global__ void mean_kernel(float* __restrict__ out) {
    const int t = threadIdx.x;   // 64
    float v = g_bloss[t];
#pragma unroll
    for (int o = 16; o > 0; o >>= 1) v += __shfl_down_sync(0xffffffffu, v, o);
    __shared__ float warp0, warp1;
    if (t == 0)  warp0 = v;
    if (t == 32) warp1 = v;
    __syncthreads();
    if (t == 0) out[0] = (warp0 + warp1) / (float)BB;
}

// ---------------------------------------------------------------------------
extern "C" void kernel_launch(void* const* d_in, const int* in_sizes, int n_in,
                              void* d_out, int out_size) {
    const float* A  = (const float*)d_in[0];
    const float* P  = (const float*)d_in[1];
    const float* Nt = (const float*)d_in[2];
    const char*  MA = (const char*)d_in[3];
    const char*  MP = (const char*)d_in[4];
    const char*  MN = (const char*)d_in[5];
    float* out = (float*)d_out;

    loss_kernel<<<BB * HH, 128>>>(A, P, Nt, MA, MP, MN);
    perb_kernel<<<BB, 288>>>();
    mean_kernel<<<1, 64>>>(out);
}